// round 5
// baseline (speedup 1.0000x reference)
#include <cuda_runtime.h>
#include <math.h>
#include <stdint.h>

#define BSZ 4
#define DIMC 256
#define LSEQ 4096
#define DIN 512
#define DST 16
#define DTR 16
#define NTOK (BSZ * LSEQ)   // 16384
#define TC 128              // scan chunk length
#define NCH (LSEQ / TC)     // 32 chunks

// -------- scratch (device globals; no allocation) --------
__device__ float g_xn[NTOK * DIMC];
__device__ float g_xz[NTOK * 2 * DIN];    // xi | z
__device__ float g_u[NTOK * DIN];
__device__ float g_dbl[NTOK * 48];        // dt|B|C
__device__ float g_y[NTOK * DIN];
__device__ float g_hE[BSZ * NCH * DIN * DST];
__device__ float g_aP[BSZ * NCH * DIN * DST];
__device__ float g_h0[BSZ * NCH * DIN * DST];

// ============================================================
// helpers
// ============================================================
__device__ __forceinline__ uint32_t smem_u32(const void* p) {
    uint32_t a;
    asm("{ .reg .u64 t; cvta.to.shared.u64 t, %1; cvt.u32.u64 %0, t; }"
        : "=r"(a) : "l"(p));
    return a;
}

__device__ __forceinline__ void cp16(uint32_t dst, const void* src, bool pred) {
    int sz = pred ? 16 : 0;
    asm volatile("cp.async.cg.shared.global [%0], [%1], 16, %2;"
                 :: "r"(dst), "l"(src), "r"(sz) : "memory");
}

__device__ __forceinline__ void spl(float v, uint32_t& h, uint32_t& l) {
    uint32_t u = __float_as_uint(v);
    h = u & 0xffffe000u;
    l = __float_as_uint(v - __uint_as_float(h));
}

__device__ __forceinline__ void mma8(float* d, const uint32_t* a,
                                     uint32_t b0, uint32_t b1) {
    asm volatile(
        "mma.sync.aligned.m16n8k8.row.col.f32.tf32.tf32.f32 "
        "{%0,%1,%2,%3}, {%4,%5,%6,%7}, {%8,%9}, {%0,%1,%2,%3};"
        : "+f"(d[0]), "+f"(d[1]), "+f"(d[2]), "+f"(d[3])
        : "r"(a[0]), "r"(a[1]), "r"(a[2]), "r"(a[3]), "r"(b0), "r"(b1));
}

// ============================================================
// split-tf32 mma GEMM: C[M,N] = A[M,K] * B[N,K]^T  (3xTF32)
//   CTA tile 128 x N_TILE, BK=32, 8 warps (warp tile 32 x N_TILE/2)
//   OUT_MODE 0: C[m*ldC + n] row-major
//   OUT_MODE 1: out[b][c][l]; m = channel c, n = global token (b,l)
// ============================================================
#define GPAD 36
#define GBUF (128 * GPAD)          // floats per matrix buffer
#define GSMEM_BYTES (2 * 2 * GBUF * 4)

template<int N_TILE, int OUT_MODE>
__global__ __launch_bounds__(256, 2) void mmagemm(
    const float* __restrict__ Ag, const float* __restrict__ Bg,
    float* __restrict__ C, int K, int bRows, int ldC)
{
    extern __shared__ float s[];
    const uint32_t sbase = smem_u32(s);
    const int tid  = threadIdx.x;
    const int lane = tid & 31, wid = tid >> 5;
    const int gid  = lane >> 2, tig = lane & 3;
    const int wm   = wid & 3,  wn  = wid >> 2;
    constexpr int TN = N_TILE / 16;          // tn count (8-wide each)

    const int m0 = blockIdx.y * 128;
    const int n0 = blockIdx.x * N_TILE;
    const int NC = K >> 5;

    float acc[2][TN][4];
    #pragma unroll
    for (int i = 0; i < 2; i++)
        #pragma unroll
        for (int j = 0; j < TN; j++)
            #pragma unroll
            for (int k = 0; k < 4; k++) acc[i][j][k] = 0.f;

    auto issue = [&](int ck) {
        const int buf = ck & 1;
        const uint32_t dA = sbase + (uint32_t)(buf * 2 * GBUF) * 4u;
        const uint32_t dB = dA + (uint32_t)GBUF * 4u;
        const int k0 = ck * 32;
        #pragma unroll
        for (int i = 0; i < 4; i++) {
            int idx = tid + (i << 8);       // 0..1023
            int row = idx >> 3;             // 0..127
            int q   = idx & 7;
            cp16(dA + (uint32_t)(row * GPAD + q * 4) * 4u,
                 Ag + (size_t)(m0 + row) * K + k0 + q * 4, true);
            if (idx < N_TILE * 8) {
                bool p = (n0 + row) < bRows;
                const float* bs = Bg + (size_t)(p ? (n0 + row) : 0) * K + k0 + q * 4;
                cp16(dB + (uint32_t)(row * GPAD + q * 4) * 4u, bs, p);
            }
        }
        asm volatile("cp.async.commit_group;" ::: "memory");
    };

    issue(0);

    for (int ck = 0; ck < NC; ck++) {
        if (ck + 1 < NC) {
            issue(ck + 1);
            asm volatile("cp.async.wait_group 1;" ::: "memory");
        } else {
            asm volatile("cp.async.wait_group 0;" ::: "memory");
        }
        __syncthreads();

        const float* As = s + (ck & 1) * 2 * GBUF;
        const float* Bs = As + GBUF;
        const float* Aw = As + (wm * 32) * GPAD;
        const float* Bw = Bs + (wn * (N_TILE / 2)) * GPAD;

        #pragma unroll
        for (int ks = 0; ks < 4; ks++) {
            const int kc = ks * 8 + tig;
            uint32_t ah[2][4], al[2][4];
            #pragma unroll
            for (int tm = 0; tm < 2; tm++) {
                const float* ap = Aw + (tm * 16 + gid) * GPAD;
                float r0 = ap[kc];
                float r1 = ap[8 * GPAD + kc];
                float r2 = ap[kc + 4];
                float r3 = ap[8 * GPAD + kc + 4];
                spl(r0, ah[tm][0], al[tm][0]);
                spl(r1, ah[tm][1], al[tm][1]);
                spl(r2, ah[tm][2], al[tm][2]);
                spl(r3, ah[tm][3], al[tm][3]);
            }
            #pragma unroll
            for (int tn = 0; tn < TN; tn++) {
                const float* bp = Bw + (tn * 8 + gid) * GPAD;
                float b0 = bp[kc];
                float b1 = bp[kc + 4];
                uint32_t bh0, bh1, bl0, bl1;
                spl(b0, bh0, bl0);
                spl(b1, bh1, bl1);
                #pragma unroll
                for (int tm = 0; tm < 2; tm++) {
                    mma8(acc[tm][tn], ah[tm], bh0, bh1);
                    mma8(acc[tm][tn], al[tm], bh0, bh1);
                    mma8(acc[tm][tn], ah[tm], bl0, bl1);
                }
            }
        }
        __syncthreads();
    }

    // ---- epilogue ----
    #pragma unroll
    for (int tm = 0; tm < 2; tm++) {
        int m = m0 + wm * 32 + tm * 16 + gid;
        #pragma unroll
        for (int tn = 0; tn < TN; tn++) {
            int n = n0 + wn * (N_TILE / 2) + tn * 8 + tig * 2;
            if (OUT_MODE == 0) {
                if (n + 2 <= bRows) {
                    float2 v0 = make_float2(acc[tm][tn][0], acc[tm][tn][1]);
                    float2 v1 = make_float2(acc[tm][tn][2], acc[tm][tn][3]);
                    *(float2*)&C[(size_t)m * ldC + n] = v0;
                    *(float2*)&C[(size_t)(m + 8) * ldC + n] = v1;
                }
            } else {
                int bb = n >> 12;
                int l  = n & 4095;
                size_t base = ((size_t)bb * DIMC + m) * LSEQ + l;
                float2 v0 = make_float2(acc[tm][tn][0], acc[tm][tn][1]);
                float2 v1 = make_float2(acc[tm][tn][2], acc[tm][tn][3]);
                *(float2*)&C[base] = v0;
                *(float2*)&C[base + (size_t)8 * LSEQ] = v1;
            }
        }
    }
}

// ============================================================
// 1. flatten + pe + LayerNorm  -> g_xn (token-major [m][c])
// ============================================================
__global__ __launch_bounds__(256) void ln_kernel(
    const float* __restrict__ x, const float* __restrict__ pe,
    const float* __restrict__ nw, const float* __restrict__ nb)
{
    __shared__ float sx[DIMC][33];
    int b  = blockIdx.y;
    int l0 = blockIdx.x * 32;
    int tid = threadIdx.x;

    const float* xb = x + (size_t)b * DIMC * LSEQ;
    for (int idx = tid; idx < DIMC * 32; idx += 256) {
        int c = idx >> 5, li = idx & 31;
        sx[c][li] = xb[(size_t)c * LSEQ + l0 + li];
    }
    __syncthreads();

    int warp = tid >> 5, lane = tid & 31;
    for (int tok = warp; tok < 32; tok += 8) {
        int l = l0 + tok;
        float v[8];
        float s = 0.f;
        #pragma unroll
        for (int k = 0; k < 8; k++) {
            int c = lane + 32 * k;
            v[k] = sx[c][tok] + pe[(size_t)l * DIMC + c];
            s += v[k];
        }
        #pragma unroll
        for (int off = 16; off; off >>= 1) s += __shfl_xor_sync(~0u, s, off);
        float mu = s * (1.f / DIMC);
        float vs = 0.f;
        #pragma unroll
        for (int k = 0; k < 8; k++) { float d = v[k] - mu; vs += d * d; }
        #pragma unroll
        for (int off = 16; off; off >>= 1) vs += __shfl_xor_sync(~0u, vs, off);
        float inv = rsqrtf(vs * (1.f / DIMC) + 1e-5f);
        int m = b * LSEQ + l;
        #pragma unroll
        for (int k = 0; k < 8; k++) {
            int c = lane + 32 * k;
            g_xn[(size_t)m * DIMC + c] = (v[k] - mu) * inv * nw[c] + nb[c];
        }
    }
}

// ============================================================
// 3. causal conv1d(k=4) + bias + SiLU  -> g_u
// ============================================================
__global__ __launch_bounds__(256) void conv_kernel(
    const float* __restrict__ cw, const float* __restrict__ cb)
{
    int idx = blockIdx.x * 256 + threadIdx.x;
    if (idx >= NTOK * DIN) return;
    int e = idx & 511;
    int m = idx >> 9;
    int l = m & 4095;
    float acc = cb[e];
    #pragma unroll
    for (int j = 0; j < 4; j++) {
        int ls = l - 3 + j;
        if (ls >= 0)
            acc = fmaf(g_xz[(size_t)(m - 3 + j) * 1024 + e], cw[e * 4 + j], acc);
    }
    g_u[idx] = acc / (1.f + __expf(-acc));
}

// ============================================================
// 5. chunked parallel selective scan (dt_proj+softplus fused)
// ============================================================
template<int PHASE>
__global__ __launch_bounds__(256) void scan_phase(
    const float* __restrict__ A_log, const float* __restrict__ Dp,
    const float* __restrict__ dtw, const float* __restrict__ dtb)
{
    __shared__ float sD[TC * 16];
    __shared__ float sU[TC * 16];
    __shared__ float sB[TC * 16];
    __shared__ float sC[TC * 16];
    __shared__ float sZ[TC * 16];
    __shared__ float sY[TC * 16];
    __shared__ float sDT[TC * 16];
    __shared__ float swdt[16 * 17];
    __shared__ float sbias[16];

    int ch   = blockIdx.x;
    int dgrp = blockIdx.y;
    int b    = blockIdx.z;
    int tid  = threadIdx.x;
    int d0   = dgrp * 16;
    int m0   = b * LSEQ + ch * TC;

    // dt_proj weights for this channel group
    {
        int dd = tid >> 4, r = tid & 15;
        swdt[dd * 17 + r] = dtw[(d0 + dd) * DTR + r];
        if (tid < 16) sbias[tid] = dtb[d0 + tid];
    }

    for (int idx = tid; idx < TC * 16; idx += 256) {
        int t = idx >> 4, dd = idx & 15;
        size_t g = (size_t)(m0 + t) * DIN + d0 + dd;
        sU[idx] = g_u[g];
        if (PHASE) sZ[idx] = g_xz[(size_t)(m0 + t) * 1024 + DIN + d0 + dd];
    }
    for (int idx = tid; idx < TC * 48; idx += 256) {
        int t = idx / 48, c = idx % 48;
        float v = g_dbl[(size_t)(m0 + t) * 48 + c];
        if (c < 16)       sDT[t * 16 + c] = v;
        else if (c < 32)  sB[t * 16 + (c - 16)] = v;
        else              sC[t * 16 + (c - 32)] = v;
    }
    __syncthreads();

    // delta = softplus(dt @ wdt^T + bias)
    for (int idx = tid; idx < TC * 16; idx += 256) {
        int t = idx >> 4, dd = idx & 15;
        float acc = sbias[dd];
        #pragma unroll
        for (int r = 0; r < 16; r++)
            acc = fmaf(sDT[t * 16 + r], swdt[dd * 17 + r], acc);
        sD[idx] = (acc > 20.f) ? acc : log1pf(__expf(acc));
    }
    __syncthreads();

    int warp = tid >> 5, lane = tid & 31;
    int half = lane >> 4, n = lane & 15;
    int dd = warp * 2 + half;
    int d  = d0 + dd;

    float An = -__expf(A_log[d * DST + n]);
    float h, aP = 1.f;
    if (PHASE) h = g_h0[(((size_t)b * NCH + ch) * DIN + d) * DST + n];
    else       h = 0.f;
    float Dv = PHASE ? Dp[d] : 0.f;

    #pragma unroll 4
    for (int t = 0; t < TC; t++) {
        float de = sD[t * 16 + dd];
        float ut = sU[t * 16 + dd];
        float Bn = sB[t * 16 + n];
        float dA = __expf(de * An);
        h = fmaf(dA, h, de * ut * Bn);
        if (PHASE) {
            float p = h * sC[t * 16 + n];
            p += __shfl_xor_sync(~0u, p, 8, 16);
            p += __shfl_xor_sync(~0u, p, 4, 16);
            p += __shfl_xor_sync(~0u, p, 2, 16);
            p += __shfl_xor_sync(~0u, p, 1, 16);
            if (n == 0) {
                float zt = sZ[t * 16 + dd];
                float yv = p + ut * Dv;
                yv *= zt / (1.f + __expf(-zt));
                sY[t * 16 + dd] = yv;
            }
        } else {
            aP *= dA;
        }
    }

    if (PHASE) {
        __syncthreads();
        for (int idx = tid; idx < TC * 16; idx += 256) {
            int t = idx >> 4, ddw = idx & 15;
            g_y[(size_t)(m0 + t) * DIN + d0 + ddw] = sY[idx];
        }
    } else {
        size_t o = (((size_t)b * NCH + ch) * DIN + d) * DST + n;
        g_hE[o] = h;
        g_aP[o] = aP;
    }
}

__global__ __launch_bounds__(256) void scan_combine()
{
    int idx = blockIdx.x * 256 + threadIdx.x;
    if (idx >= BSZ * DIN * DST) return;
    int b  = idx / (DIN * DST);
    int dn = idx % (DIN * DST);
    float h = 0.f;
    #pragma unroll 4
    for (int ch = 0; ch < NCH; ch++) {
        size_t o = ((size_t)b * NCH + ch) * (DIN * DST) + dn;
        g_h0[o] = h;
        h = fmaf(g_aP[o], h, g_hE[o]);
    }
}

// ============================================================
// launch
// ============================================================
extern "C" void kernel_launch(void* const* d_in, const int* in_sizes, int n_in,
                              void* d_out, int out_size)
{
    const float* x        = (const float*)d_in[0];
    const float* pe       = (const float*)d_in[1];
    const float* norm_w   = (const float*)d_in[3];
    const float* norm_b   = (const float*)d_in[4];
    const float* in_proj  = (const float*)d_in[5];
    const float* conv_w   = (const float*)d_in[6];
    const float* conv_b   = (const float*)d_in[7];
    const float* x_proj   = (const float*)d_in[8];
    const float* dt_proj  = (const float*)d_in[9];
    const float* dt_b     = (const float*)d_in[10];
    const float* A_log    = (const float*)d_in[11];
    const float* Dp       = (const float*)d_in[12];
    const float* out_proj = (const float*)d_in[13];
    float* out = (float*)d_out;

    float* xn  = nullptr; cudaGetSymbolAddress((void**)&xn,  g_xn);
    float* xz  = nullptr; cudaGetSymbolAddress((void**)&xz,  g_xz);
    float* u   = nullptr; cudaGetSymbolAddress((void**)&u,   g_u);
    float* dbl = nullptr; cudaGetSymbolAddress((void**)&dbl, g_dbl);
    float* y   = nullptr; cudaGetSymbolAddress((void**)&y,   g_y);

    cudaFuncSetAttribute((const void*)mmagemm<128, 0>,
        cudaFuncAttributeMaxDynamicSharedMemorySize, GSMEM_BYTES);
    cudaFuncSetAttribute((const void*)mmagemm<64, 0>,
        cudaFuncAttributeMaxDynamicSharedMemorySize, GSMEM_BYTES);
    cudaFuncSetAttribute((const void*)mmagemm<128, 1>,
        cudaFuncAttributeMaxDynamicSharedMemorySize, GSMEM_BYTES);

    // 1. pe + layernorm
    ln_kernel<<<dim3(LSEQ / 32, BSZ), 256>>>(x, pe, norm_w, norm_b);

    // 2. in_proj: xz[16384,1024] = xn[16384,256] @ in_proj^T
    mmagemm<128, 0><<<dim3(1024 / 128, NTOK / 128), 256, GSMEM_BYTES>>>(
        xn, in_proj, xz, DIMC, 2 * DIN, 2 * DIN);

    // 3. conv + silu
    conv_kernel<<<(NTOK * DIN) / 256, 256>>>(conv_w, conv_b);

    // 4. x_proj: dbl[16384,48] = u @ x_proj^T  (N_TILE=64)
    mmagemm<64, 0><<<dim3(1, NTOK / 128), 256, GSMEM_BYTES>>>(
        u, x_proj, dbl, DIN, 48, 48);

    // 5+6. chunked parallel scan (dt_proj fused into phases)
    scan_phase<0><<<dim3(NCH, 32, BSZ), 256>>>(A_log, Dp, dt_proj, dt_b);
    scan_combine<<<(BSZ * DIN * DST) / 256, 256>>>();
    scan_phase<1><<<dim3(NCH, 32, BSZ), 256>>>(A_log, Dp, dt_proj, dt_b);

    // 7. out_proj: A = out_proj_w (channels as M), B = g_y (tokens as N),
    //    transposed store lands contiguous along l
    mmagemm<128, 1><<<dim3(NTOK / 128, DIMC / 128), 256, GSMEM_BYTES>>>(
        out_proj, y, out, DIN, NTOK, 0);
}

// round 6
// speedup vs baseline: 1.0876x; 1.0876x over previous
#include <cuda_runtime.h>
#include <math.h>
#include <stdint.h>

#define BSZ 4
#define DIMC 256
#define LSEQ 4096
#define DIN 512
#define DST 16
#define DTR 16
#define NTOK (BSZ * LSEQ)   // 16384
#define TC 128              // scan chunk length
#define NCH (LSEQ / TC)     // 32 chunks

// -------- scratch (device globals; no allocation) --------
__device__ float g_xn[NTOK * DIMC];
__device__ float g_xz[NTOK * 2 * DIN];    // xi | z
__device__ float g_u[NTOK * DIN];
__device__ float g_dbl[NTOK * 48];        // dt|B|C
__device__ float g_y[NTOK * DIN];
__device__ float g_hE[BSZ * NCH * DIN * DST];
__device__ float g_aP[BSZ * NCH * DIN * DST];
__device__ float g_h0[BSZ * NCH * DIN * DST];

// ============================================================
// helpers
// ============================================================
__device__ __forceinline__ uint32_t smem_u32(const void* p) {
    uint32_t a;
    asm("{ .reg .u64 t; cvta.to.shared.u64 t, %1; cvt.u32.u64 %0, t; }"
        : "=r"(a) : "l"(p));
    return a;
}

__device__ __forceinline__ void cp16(uint32_t dst, const void* src, bool pred) {
    int sz = pred ? 16 : 0;
    asm volatile("cp.async.cg.shared.global [%0], [%1], 16, %2;"
                 :: "r"(dst), "l"(src), "r"(sz) : "memory");
}

__device__ __forceinline__ void spl(float v, uint32_t& h, uint32_t& l) {
    uint32_t u = __float_as_uint(v);
    h = u & 0xffffe000u;
    l = __float_as_uint(v - __uint_as_float(h));
}

__device__ __forceinline__ void mma8(float* d, const uint32_t* a,
                                     uint32_t b0, uint32_t b1) {
    asm volatile(
        "mma.sync.aligned.m16n8k8.row.col.f32.tf32.tf32.f32 "
        "{%0,%1,%2,%3}, {%4,%5,%6,%7}, {%8,%9}, {%0,%1,%2,%3};"
        : "+f"(d[0]), "+f"(d[1]), "+f"(d[2]), "+f"(d[3])
        : "r"(a[0]), "r"(a[1]), "r"(a[2]), "r"(a[3]), "r"(b0), "r"(b1));
}

// ============================================================
// split-tf32 mma GEMM: C[M,N] = A[M,K] * B[N,K]^T  (3xTF32)
//   CTA tile 128 x N_TILE, BK=32, 8 warps (warp tile 32 x N_TILE/2)
//   OUT_MODE 0: C[m*ldC + n] row-major
//   OUT_MODE 1: out[b][c][l]; m = channel c, n = global token (b,l)
// ============================================================
#define GPAD 36
#define GBUF (128 * GPAD)          // floats per matrix buffer
#define GSMEM_BYTES (2 * 2 * GBUF * 4)

template<int N_TILE, int OUT_MODE>
__global__ __launch_bounds__(256, 2) void mmagemm(
    const float* __restrict__ Ag, const float* __restrict__ Bg,
    float* __restrict__ C, int K, int bRows, int ldC)
{
    extern __shared__ float s[];
    const uint32_t sbase = smem_u32(s);
    const int tid  = threadIdx.x;
    const int lane = tid & 31, wid = tid >> 5;
    const int gid  = lane >> 2, tig = lane & 3;
    const int wm   = wid & 3,  wn  = wid >> 2;
    constexpr int TN = N_TILE / 16;

    const int m0 = blockIdx.y * 128;
    const int n0 = blockIdx.x * N_TILE;
    const int NC = K >> 5;

    float acc[2][TN][4];
    #pragma unroll
    for (int i = 0; i < 2; i++)
        #pragma unroll
        for (int j = 0; j < TN; j++)
            #pragma unroll
            for (int k = 0; k < 4; k++) acc[i][j][k] = 0.f;

    auto issue = [&](int ck) {
        const int buf = ck & 1;
        const uint32_t dA = sbase + (uint32_t)(buf * 2 * GBUF) * 4u;
        const uint32_t dB = dA + (uint32_t)GBUF * 4u;
        const int k0 = ck * 32;
        #pragma unroll
        for (int i = 0; i < 4; i++) {
            int idx = tid + (i << 8);
            int row = idx >> 3;
            int q   = idx & 7;
            cp16(dA + (uint32_t)(row * GPAD + q * 4) * 4u,
                 Ag + (size_t)(m0 + row) * K + k0 + q * 4, true);
            if (idx < N_TILE * 8) {
                bool p = (n0 + row) < bRows;
                const float* bs = Bg + (size_t)(p ? (n0 + row) : 0) * K + k0 + q * 4;
                cp16(dB + (uint32_t)(row * GPAD + q * 4) * 4u, bs, p);
            }
        }
        asm volatile("cp.async.commit_group;" ::: "memory");
    };

    issue(0);

    for (int ck = 0; ck < NC; ck++) {
        if (ck + 1 < NC) {
            issue(ck + 1);
            asm volatile("cp.async.wait_group 1;" ::: "memory");
        } else {
            asm volatile("cp.async.wait_group 0;" ::: "memory");
        }
        __syncthreads();

        const float* As = s + (ck & 1) * 2 * GBUF;
        const float* Bs = As + GBUF;
        const float* Aw = As + (wm * 32) * GPAD;
        const float* Bw = Bs + (wn * (N_TILE / 2)) * GPAD;

        #pragma unroll
        for (int ks = 0; ks < 4; ks++) {
            const int kc = ks * 8 + tig;
            uint32_t ah[2][4], al[2][4];
            #pragma unroll
            for (int tm = 0; tm < 2; tm++) {
                const float* ap = Aw + (tm * 16 + gid) * GPAD;
                float r0 = ap[kc];
                float r1 = ap[8 * GPAD + kc];
                float r2 = ap[kc + 4];
                float r3 = ap[8 * GPAD + kc + 4];
                spl(r0, ah[tm][0], al[tm][0]);
                spl(r1, ah[tm][1], al[tm][1]);
                spl(r2, ah[tm][2], al[tm][2]);
                spl(r3, ah[tm][3], al[tm][3]);
            }
            #pragma unroll
            for (int tn = 0; tn < TN; tn++) {
                const float* bp = Bw + (tn * 8 + gid) * GPAD;
                float b0 = bp[kc];
                float b1 = bp[kc + 4];
                uint32_t bh0, bh1, bl0, bl1;
                spl(b0, bh0, bl0);
                spl(b1, bh1, bl1);
                #pragma unroll
                for (int tm = 0; tm < 2; tm++) {
                    mma8(acc[tm][tn], ah[tm], bh0, bh1);
                    mma8(acc[tm][tn], al[tm], bh0, bh1);
                    mma8(acc[tm][tn], ah[tm], bl0, bl1);
                }
            }
        }
        __syncthreads();
    }

    #pragma unroll
    for (int tm = 0; tm < 2; tm++) {
        int m = m0 + wm * 32 + tm * 16 + gid;
        #pragma unroll
        for (int tn = 0; tn < TN; tn++) {
            int n = n0 + wn * (N_TILE / 2) + tn * 8 + tig * 2;
            if (OUT_MODE == 0) {
                if (n + 2 <= bRows) {
                    float2 v0 = make_float2(acc[tm][tn][0], acc[tm][tn][1]);
                    float2 v1 = make_float2(acc[tm][tn][2], acc[tm][tn][3]);
                    *(float2*)&C[(size_t)m * ldC + n] = v0;
                    *(float2*)&C[(size_t)(m + 8) * ldC + n] = v1;
                }
            } else {
                int bb = n >> 12;
                int l  = n & 4095;
                size_t base = ((size_t)bb * DIMC + m) * LSEQ + l;
                float2 v0 = make_float2(acc[tm][tn][0], acc[tm][tn][1]);
                float2 v1 = make_float2(acc[tm][tn][2], acc[tm][tn][3]);
                *(float2*)&C[base] = v0;
                *(float2*)&C[base + (size_t)8 * LSEQ] = v1;
            }
        }
    }
}

// ============================================================
// 1. flatten + pe + LayerNorm  -> g_xn (token-major [m][c])
// ============================================================
__global__ __launch_bounds__(256) void ln_kernel(
    const float* __restrict__ x, const float* __restrict__ pe,
    const float* __restrict__ nw, const float* __restrict__ nb)
{
    __shared__ float sx[DIMC][33];
    int b  = blockIdx.y;
    int l0 = blockIdx.x * 32;
    int tid = threadIdx.x;

    const float* xb = x + (size_t)b * DIMC * LSEQ;
    for (int idx = tid; idx < DIMC * 32; idx += 256) {
        int c = idx >> 5, li = idx & 31;
        sx[c][li] = xb[(size_t)c * LSEQ + l0 + li];
    }
    __syncthreads();

    int warp = tid >> 5, lane = tid & 31;
    for (int tok = warp; tok < 32; tok += 8) {
        int l = l0 + tok;
        float v[8];
        float s = 0.f;
        #pragma unroll
        for (int k = 0; k < 8; k++) {
            int c = lane + 32 * k;
            v[k] = sx[c][tok] + pe[(size_t)l * DIMC + c];
            s += v[k];
        }
        #pragma unroll
        for (int off = 16; off; off >>= 1) s += __shfl_xor_sync(~0u, s, off);
        float mu = s * (1.f / DIMC);
        float vs = 0.f;
        #pragma unroll
        for (int k = 0; k < 8; k++) { float d = v[k] - mu; vs += d * d; }
        #pragma unroll
        for (int off = 16; off; off >>= 1) vs += __shfl_xor_sync(~0u, vs, off);
        float inv = rsqrtf(vs * (1.f / DIMC) + 1e-5f);
        int m = b * LSEQ + l;
        #pragma unroll
        for (int k = 0; k < 8; k++) {
            int c = lane + 32 * k;
            g_xn[(size_t)m * DIMC + c] = (v[k] - mu) * inv * nw[c] + nb[c];
        }
    }
}

// ============================================================
// 3. causal conv1d(k=4) + bias + SiLU  -> g_u
// ============================================================
__global__ __launch_bounds__(256) void conv_kernel(
    const float* __restrict__ cw, const float* __restrict__ cb)
{
    int idx = blockIdx.x * 256 + threadIdx.x;
    if (idx >= NTOK * DIN) return;
    int e = idx & 511;
    int m = idx >> 9;
    int l = m & 4095;
    float acc = cb[e];
    #pragma unroll
    for (int j = 0; j < 4; j++) {
        int ls = l - 3 + j;
        if (ls >= 0)
            acc = fmaf(g_xz[(size_t)(m - 3 + j) * 1024 + e], cw[e * 4 + j], acc);
    }
    g_u[idx] = acc / (1.f + __expf(-acc));
}

// ============================================================
// 5. chunked parallel selective scan (dt_proj+softplus fused)
//    dynamic smem layout (floats):
//      sU[0,2048) sB[2048,4096) sC[4096,6144) sD[6144,8192)
//      swdt[8192,8464) sbias[8464,8480)
//      PHASE1 only: sZ[8480,10528) sY[10528,12576)
// ============================================================
#define S0_BYTES (8480 * 4)
#define S1_BYTES (12576 * 4)

template<int PHASE>
__global__ __launch_bounds__(256) void scan_phase(
    const float* __restrict__ A_log, const float* __restrict__ Dp,
    const float* __restrict__ dtw, const float* __restrict__ dtb)
{
    extern __shared__ float sm[];
    float* sU    = sm;
    float* sB    = sm + 2048;
    float* sC    = sm + 4096;
    float* sD    = sm + 6144;      // staged dt, then delta (in place)
    float* swdt  = sm + 8192;      // 16 x 17
    float* sbias = sm + 8464;
    float* sZ    = sm + 8480;
    float* sY    = sm + 10528;

    int ch   = blockIdx.x;
    int dgrp = blockIdx.y;
    int b    = blockIdx.z;
    int tid  = threadIdx.x;
    int d0   = dgrp * 16;
    int m0   = b * LSEQ + ch * TC;

    {
        int dd = tid >> 4, r = tid & 15;
        swdt[dd * 17 + r] = dtw[(d0 + dd) * DTR + r];
        if (tid < 16) sbias[tid] = dtb[d0 + tid];
    }

    for (int idx = tid; idx < TC * 16; idx += 256) {
        int t = idx >> 4, dd = idx & 15;
        size_t g = (size_t)(m0 + t) * DIN + d0 + dd;
        sU[idx] = g_u[g];
        if (PHASE) sZ[idx] = g_xz[(size_t)(m0 + t) * 1024 + DIN + d0 + dd];
    }
    for (int idx = tid; idx < TC * 48; idx += 256) {
        int t = idx / 48, c = idx % 48;
        float v = g_dbl[(size_t)(m0 + t) * 48 + c];
        if (c < 16)       sD[t * 16 + c] = v;
        else if (c < 32)  sB[t * 16 + (c - 16)] = v;
        else              sC[t * 16 + (c - 32)] = v;
    }
    __syncthreads();

    // delta = softplus(dt @ wdt^T + bias), computed in regs, written in place
    float dv[8];
    #pragma unroll
    for (int i = 0; i < 8; i++) {
        int idx = tid + i * 256;
        int t = idx >> 4, dd = idx & 15;
        float acc = sbias[dd];
        #pragma unroll
        for (int r = 0; r < 16; r++)
            acc = fmaf(sD[t * 16 + r], swdt[dd * 17 + r], acc);
        dv[i] = (acc > 20.f) ? acc : log1pf(__expf(acc));
    }
    __syncthreads();
    #pragma unroll
    for (int i = 0; i < 8; i++) sD[tid + i * 256] = dv[i];
    __syncthreads();

    int warp = tid >> 5, lane = tid & 31;
    int half = lane >> 4, n = lane & 15;
    int dd = warp * 2 + half;
    int d  = d0 + dd;

    float An = -__expf(A_log[d * DST + n]);
    float h, aP = 1.f;
    if (PHASE) h = g_h0[(((size_t)b * NCH + ch) * DIN + d) * DST + n];
    else       h = 0.f;
    float Dv = PHASE ? Dp[d] : 0.f;

    #pragma unroll 4
    for (int t = 0; t < TC; t++) {
        float de = sD[t * 16 + dd];
        float ut = sU[t * 16 + dd];
        float Bn = sB[t * 16 + n];
        float dA = __expf(de * An);
        h = fmaf(dA, h, de * ut * Bn);
        if (PHASE) {
            float p = h * sC[t * 16 + n];
            p += __shfl_xor_sync(~0u, p, 8, 16);
            p += __shfl_xor_sync(~0u, p, 4, 16);
            p += __shfl_xor_sync(~0u, p, 2, 16);
            p += __shfl_xor_sync(~0u, p, 1, 16);
            if (n == 0) {
                float zt = sZ[t * 16 + dd];
                float yv = p + ut * Dv;
                yv *= zt / (1.f + __expf(-zt));
                sY[t * 16 + dd] = yv;
            }
        } else {
            aP *= dA;
        }
    }

    if (PHASE) {
        __syncthreads();
        for (int idx = tid; idx < TC * 16; idx += 256) {
            int t = idx >> 4, ddw = idx & 15;
            g_y[(size_t)(m0 + t) * DIN + d0 + ddw] = sY[idx];
        }
    } else {
        size_t o = (((size_t)b * NCH + ch) * DIN + d) * DST + n;
        g_hE[o] = h;
        g_aP[o] = aP;
    }
}

__global__ __launch_bounds__(256) void scan_combine()
{
    int idx = blockIdx.x * 256 + threadIdx.x;
    if (idx >= BSZ * DIN * DST) return;
    int b  = idx / (DIN * DST);
    int dn = idx % (DIN * DST);
    float h = 0.f;
    #pragma unroll 4
    for (int ch = 0; ch < NCH; ch++) {
        size_t o = ((size_t)b * NCH + ch) * (DIN * DST) + dn;
        g_h0[o] = h;
        h = fmaf(g_aP[o], h, g_hE[o]);
    }
}

// ============================================================
// launch
// ============================================================
extern "C" void kernel_launch(void* const* d_in, const int* in_sizes, int n_in,
                              void* d_out, int out_size)
{
    const float* x        = (const float*)d_in[0];
    const float* pe       = (const float*)d_in[1];
    const float* norm_w   = (const float*)d_in[3];
    const float* norm_b   = (const float*)d_in[4];
    const float* in_proj  = (const float*)d_in[5];
    const float* conv_w   = (const float*)d_in[6];
    const float* conv_b   = (const float*)d_in[7];
    const float* x_proj   = (const float*)d_in[8];
    const float* dt_proj  = (const float*)d_in[9];
    const float* dt_b     = (const float*)d_in[10];
    const float* A_log    = (const float*)d_in[11];
    const float* Dp       = (const float*)d_in[12];
    const float* out_proj = (const float*)d_in[13];
    float* out = (float*)d_out;

    float* xn  = nullptr; cudaGetSymbolAddress((void**)&xn,  g_xn);
    float* xz  = nullptr; cudaGetSymbolAddress((void**)&xz,  g_xz);
    float* u   = nullptr; cudaGetSymbolAddress((void**)&u,   g_u);
    float* dbl = nullptr; cudaGetSymbolAddress((void**)&dbl, g_dbl);
    float* y   = nullptr; cudaGetSymbolAddress((void**)&y,   g_y);

    cudaFuncSetAttribute((const void*)mmagemm<128, 0>,
        cudaFuncAttributeMaxDynamicSharedMemorySize, GSMEM_BYTES);
    cudaFuncSetAttribute((const void*)mmagemm<64, 0>,
        cudaFuncAttributeMaxDynamicSharedMemorySize, GSMEM_BYTES);
    cudaFuncSetAttribute((const void*)mmagemm<128, 1>,
        cudaFuncAttributeMaxDynamicSharedMemorySize, GSMEM_BYTES);
    cudaFuncSetAttribute((const void*)scan_phase<1>,
        cudaFuncAttributeMaxDynamicSharedMemorySize, S1_BYTES);

    // 1. pe + layernorm
    ln_kernel<<<dim3(LSEQ / 32, BSZ), 256>>>(x, pe, norm_w, norm_b);

    // 2. in_proj: xz[16384,1024] = xn[16384,256] @ in_proj^T
    mmagemm<128, 0><<<dim3(1024 / 128, NTOK / 128), 256, GSMEM_BYTES>>>(
        xn, in_proj, xz, DIMC, 2 * DIN, 2 * DIN);

    // 3. conv + silu
    conv_kernel<<<(NTOK * DIN) / 256, 256>>>(conv_w, conv_b);

    // 4. x_proj: dbl[16384,48] = u @ x_proj^T  (N_TILE=64)
    mmagemm<64, 0><<<dim3(1, NTOK / 128), 256, GSMEM_BYTES>>>(
        u, x_proj, dbl, DIN, 48, 48);

    // 5+6. chunked parallel scan (dt_proj fused into phases)
    scan_phase<0><<<dim3(NCH, 32, BSZ), 256, S0_BYTES>>>(A_log, Dp, dt_proj, dt_b);
    scan_combine<<<(BSZ * DIN * DST) / 256, 256>>>();
    scan_phase<1><<<dim3(NCH, 32, BSZ), 256, S1_BYTES>>>(A_log, Dp, dt_proj, dt_b);

    // 7. out_proj: A = out_proj_w (channels as M), B = g_y (tokens as N)
    mmagemm<128, 1><<<dim3(NTOK / 128, DIMC / 128), 256, GSMEM_BYTES>>>(
        out_proj, y, out, DIN, NTOK, 0);
}

// round 7
// speedup vs baseline: 1.2801x; 1.1771x over previous
#include <cuda_runtime.h>
#include <cuda_bf16.h>
#include <math.h>
#include <stdint.h>

#define BSZ 4
#define DIMC 256
#define LSEQ 4096
#define DIN 512
#define DST 16
#define DTR 16
#define NTOK (BSZ * LSEQ)   // 16384
#define TC 128              // scan chunk length
#define NCH (LSEQ / TC)     // 32 chunks

// -------- scratch (device globals; no allocation) --------
__device__ float g_xn[NTOK * DIMC];
__device__ float g_xz[NTOK * 2 * DIN];    // xi | z
__device__ float g_u[NTOK * DIN];
__device__ float g_dbl[NTOK * 48];        // dt|B|C
__device__ float g_delta[NTOK * DIN];
__device__ float g_y[NTOK * DIN];
__device__ float g_wdtT[DTR * DIN];
__device__ float g_hE[BSZ * NCH * DIN * DST];
__device__ float g_aP[BSZ * NCH * DIN * DST];
__device__ float g_h0[BSZ * NCH * DIN * DST];

// ============================================================
// helpers
// ============================================================
__device__ __forceinline__ uint32_t pack2(float a, float b) {
    __nv_bfloat162 t = __floats2bfloat162_rn(a, b);
    return *reinterpret_cast<uint32_t*>(&t);
}

__device__ __forceinline__ void hilo4(float4 v, uint2& hi, uint2& lo) {
    float hx = __bfloat162float(__float2bfloat16(v.x));
    float hy = __bfloat162float(__float2bfloat16(v.y));
    float hz = __bfloat162float(__float2bfloat16(v.z));
    float hw = __bfloat162float(__float2bfloat16(v.w));
    hi.x = pack2(hx, hy);
    hi.y = pack2(hz, hw);
    lo.x = pack2(v.x - hx, v.y - hy);
    lo.y = pack2(v.z - hz, v.w - hw);
}

__device__ __forceinline__ void mma16(float* d, const uint32_t* a,
                                      uint32_t b0, uint32_t b1) {
    asm volatile(
        "mma.sync.aligned.m16n8k16.row.col.f32.bf16.bf16.f32 "
        "{%0,%1,%2,%3}, {%4,%5,%6,%7}, {%8,%9}, {%0,%1,%2,%3};"
        : "+f"(d[0]), "+f"(d[1]), "+f"(d[2]), "+f"(d[3])
        : "r"(a[0]), "r"(a[1]), "r"(a[2]), "r"(a[3]), "r"(b0), "r"(b1));
}

// ============================================================
// split-bf16 (3-term) mma GEMM: C[M,N] = A[M,K] * B[N,K]^T
//   CTA tile 128 x N_TILE, BK=32, 8 warps (warp tile 32 x N_TILE/2)
//   smem: single-buffered bf16 tiles Ah/Al/Bh/Bl, row stride 40 bf16
//   register-prefetch double buffering of global loads
//   OUT_MODE 0: C[m*ldC + n] row-major
//   OUT_MODE 1: out[b][c][l]; m = channel c, n = global token (b,l)
// ============================================================
#define SROWB 80                    // bytes per tile row (40 bf16)

template<int N_TILE, int OUT_MODE>
__global__ __launch_bounds__(256, 2) void mmagemm(
    const float* __restrict__ Ag, const float* __restrict__ Bg,
    float* __restrict__ C, int K, int bRows, int ldC)
{
    constexpr int TN = N_TILE / 16;
    constexpr int NB = (N_TILE * 8) / 256;      // B float4 quads per thread
    constexpr int TA_B = 128 * SROWB;           // A tile bytes
    constexpr int TB_B = N_TILE * SROWB;        // B tile bytes
    constexpr int AH = 0, AL = TA_B, BH = 2 * TA_B, BL = 2 * TA_B + TB_B;

    __shared__ char sm[2 * TA_B + 2 * TB_B];

    const int tid  = threadIdx.x;
    const int lane = tid & 31, wid = tid >> 5;
    const int gid  = lane >> 2, tig = lane & 3;
    const int wm   = wid & 3,  wn  = wid >> 2;

    const int m0 = blockIdx.y * 128;
    const int n0 = blockIdx.x * N_TILE;
    const int NC = K >> 5;

    float acc[2][TN][4];
    #pragma unroll
    for (int i = 0; i < 2; i++)
        #pragma unroll
        for (int j = 0; j < TN; j++)
            #pragma unroll
            for (int k = 0; k < 4; k++) acc[i][j][k] = 0.f;

    float4 avA[4], avB[NB > 0 ? NB : 1];

    auto ldg_regs = [&](int ck) {
        const int k0 = ck * 32;
        #pragma unroll
        for (int i = 0; i < 4; i++) {
            int idx = tid + (i << 8);
            int row = idx >> 3, q = idx & 7;
            avA[i] = *(const float4*)(Ag + (size_t)(m0 + row) * K + k0 + q * 4);
        }
        #pragma unroll
        for (int i = 0; i < NB; i++) {
            int idx = tid + (i << 8);
            int row = idx >> 3, q = idx & 7;
            if (n0 + row < bRows)
                avB[i] = *(const float4*)(Bg + (size_t)(n0 + row) * K + k0 + q * 4);
            else
                avB[i] = make_float4(0.f, 0.f, 0.f, 0.f);
        }
    };

    auto sts_regs = [&]() {
        #pragma unroll
        for (int i = 0; i < 4; i++) {
            int idx = tid + (i << 8);
            int row = idx >> 3, q = idx & 7;
            int byte = row * SROWB + q * 8;
            uint2 hi, lo;
            hilo4(avA[i], hi, lo);
            *(uint2*)(sm + AH + byte) = hi;
            *(uint2*)(sm + AL + byte) = lo;
        }
        #pragma unroll
        for (int i = 0; i < NB; i++) {
            int idx = tid + (i << 8);
            int row = idx >> 3, q = idx & 7;
            int byte = row * SROWB + q * 8;
            uint2 hi, lo;
            hilo4(avB[i], hi, lo);
            *(uint2*)(sm + BH + byte) = hi;
            *(uint2*)(sm + BL + byte) = lo;
        }
    };

    ldg_regs(0);

    for (int ck = 0; ck < NC; ck++) {
        sts_regs();
        __syncthreads();
        if (ck + 1 < NC) ldg_regs(ck + 1);

        #pragma unroll
        for (int ks = 0; ks < 2; ks++) {
            const int kb = ks * 32 + tig * 4;   // byte offset within row
            uint32_t ah[2][4], al[2][4];
            #pragma unroll
            for (int tm = 0; tm < 2; tm++) {
                int r0 = (wm * 32 + tm * 16 + gid) * SROWB;
                ah[tm][0] = *(const uint32_t*)(sm + AH + r0 + kb);
                ah[tm][1] = *(const uint32_t*)(sm + AH + r0 + 8 * SROWB + kb);
                ah[tm][2] = *(const uint32_t*)(sm + AH + r0 + kb + 16);
                ah[tm][3] = *(const uint32_t*)(sm + AH + r0 + 8 * SROWB + kb + 16);
                al[tm][0] = *(const uint32_t*)(sm + AL + r0 + kb);
                al[tm][1] = *(const uint32_t*)(sm + AL + r0 + 8 * SROWB + kb);
                al[tm][2] = *(const uint32_t*)(sm + AL + r0 + kb + 16);
                al[tm][3] = *(const uint32_t*)(sm + AL + r0 + 8 * SROWB + kb + 16);
            }
            #pragma unroll
            for (int tn = 0; tn < TN; tn++) {
                int rb = (wn * (N_TILE / 2) + tn * 8 + gid) * SROWB;
                uint32_t bh0 = *(const uint32_t*)(sm + BH + rb + kb);
                uint32_t bh1 = *(const uint32_t*)(sm + BH + rb + kb + 16);
                uint32_t bl0 = *(const uint32_t*)(sm + BL + rb + kb);
                uint32_t bl1 = *(const uint32_t*)(sm + BL + rb + kb + 16);
                #pragma unroll
                for (int tm = 0; tm < 2; tm++) {
                    mma16(acc[tm][tn], ah[tm], bh0, bh1);
                    mma16(acc[tm][tn], al[tm], bh0, bh1);
                    mma16(acc[tm][tn], ah[tm], bl0, bl1);
                }
            }
        }
        __syncthreads();
    }

    #pragma unroll
    for (int tm = 0; tm < 2; tm++) {
        int m = m0 + wm * 32 + tm * 16 + gid;
        #pragma unroll
        for (int tn = 0; tn < TN; tn++) {
            int n = n0 + wn * (N_TILE / 2) + tn * 8 + tig * 2;
            if (OUT_MODE == 0) {
                if (n + 2 <= bRows) {
                    float2 v0 = make_float2(acc[tm][tn][0], acc[tm][tn][1]);
                    float2 v1 = make_float2(acc[tm][tn][2], acc[tm][tn][3]);
                    *(float2*)&C[(size_t)m * ldC + n] = v0;
                    *(float2*)&C[(size_t)(m + 8) * ldC + n] = v1;
                }
            } else {
                int bb = n >> 12;
                int l  = n & 4095;
                size_t base = ((size_t)bb * DIMC + m) * LSEQ + l;
                float2 v0 = make_float2(acc[tm][tn][0], acc[tm][tn][1]);
                float2 v1 = make_float2(acc[tm][tn][2], acc[tm][tn][3]);
                *(float2*)&C[base] = v0;
                *(float2*)&C[base + (size_t)8 * LSEQ] = v1;
            }
        }
    }
}

// ============================================================
// 1. flatten + pe + LayerNorm  -> g_xn (token-major [m][c])
// ============================================================
__global__ __launch_bounds__(256) void ln_kernel(
    const float* __restrict__ x, const float* __restrict__ pe,
    const float* __restrict__ nw, const float* __restrict__ nb)
{
    __shared__ float sx[DIMC][33];
    int b  = blockIdx.y;
    int l0 = blockIdx.x * 32;
    int tid = threadIdx.x;

    const float* xb = x + (size_t)b * DIMC * LSEQ;
    for (int idx = tid; idx < DIMC * 32; idx += 256) {
        int c = idx >> 5, li = idx & 31;
        sx[c][li] = xb[(size_t)c * LSEQ + l0 + li];
    }
    __syncthreads();

    int warp = tid >> 5, lane = tid & 31;
    for (int tok = warp; tok < 32; tok += 8) {
        int l = l0 + tok;
        float v[8];
        float s = 0.f;
        #pragma unroll
        for (int k = 0; k < 8; k++) {
            int c = lane + 32 * k;
            v[k] = sx[c][tok] + pe[(size_t)l * DIMC + c];
            s += v[k];
        }
        #pragma unroll
        for (int off = 16; off; off >>= 1) s += __shfl_xor_sync(~0u, s, off);
        float mu = s * (1.f / DIMC);
        float vs = 0.f;
        #pragma unroll
        for (int k = 0; k < 8; k++) { float d = v[k] - mu; vs += d * d; }
        #pragma unroll
        for (int off = 16; off; off >>= 1) vs += __shfl_xor_sync(~0u, vs, off);
        float inv = rsqrtf(vs * (1.f / DIMC) + 1e-5f);
        int m = b * LSEQ + l;
        #pragma unroll
        for (int k = 0; k < 8; k++) {
            int c = lane + 32 * k;
            g_xn[(size_t)m * DIMC + c] = (v[k] - mu) * inv * nw[c] + nb[c];
        }
    }
}

// ============================================================
// 3. causal conv1d(k=4) + bias + SiLU  -> g_u
// ============================================================
__global__ __launch_bounds__(256) void conv_kernel(
    const float* __restrict__ cw, const float* __restrict__ cb)
{
    int idx = blockIdx.x * 256 + threadIdx.x;
    if (idx >= NTOK * DIN) return;
    int e = idx & 511;
    int m = idx >> 9;
    int l = m & 4095;
    float acc = cb[e];
    #pragma unroll
    for (int j = 0; j < 4; j++) {
        int ls = l - 3 + j;
        if (ls >= 0)
            acc = fmaf(g_xz[(size_t)(m - 3 + j) * 1024 + e], cw[e * 4 + j], acc);
    }
    g_u[idx] = acc / (1.f + __expf(-acc));
}

// ============================================================
// 4. dt_proj + softplus  (round-4 structure)
// ============================================================
__global__ void wdt_transpose_kernel(const float* __restrict__ dtw)
{
    int idx = blockIdx.x * 256 + threadIdx.x;
    if (idx < DIN * DTR) {
        int d = idx >> 4, r = idx & 15;
        g_wdtT[r * DIN + d] = dtw[d * DTR + r];
    }
}

__global__ __launch_bounds__(512) void dt_kernel(const float* __restrict__ dtb)
{
    __shared__ float sdt[16];
    int m = blockIdx.x;
    int d = threadIdx.x;
    if (d < 16) sdt[d] = g_dbl[(size_t)m * 48 + d];
    __syncthreads();
    float acc = dtb[d];
    #pragma unroll
    for (int r = 0; r < 16; r++)
        acc = fmaf(sdt[r], g_wdtT[r * DIN + d], acc);
    float sp = (acc > 20.f) ? acc : log1pf(__expf(acc));
    g_delta[(size_t)m * DIN + d] = sp;
}

// ============================================================
// 5. chunked parallel selective scan  (round-4 structure)
// ============================================================
template<int PHASE>
__global__ __launch_bounds__(256) void scan_phase(
    const float* __restrict__ A_log, const float* __restrict__ Dp)
{
    __shared__ float sD[TC * 16];
    __shared__ float sU[TC * 16];
    __shared__ float sB[TC * 16];
    __shared__ float sC[TC * 16];
    __shared__ float sZ[TC * 16];
    __shared__ float sY[TC * 16];

    int ch   = blockIdx.x;
    int dgrp = blockIdx.y;
    int b    = blockIdx.z;
    int tid  = threadIdx.x;
    int d0   = dgrp * 16;
    int m0   = b * LSEQ + ch * TC;

    for (int idx = tid; idx < TC * 16; idx += 256) {
        int t = idx >> 4, dd = idx & 15;
        size_t g = (size_t)(m0 + t) * DIN + d0 + dd;
        sD[idx] = g_delta[g];
        sU[idx] = g_u[g];
        if (PHASE) sZ[idx] = g_xz[(size_t)(m0 + t) * 1024 + DIN + d0 + dd];
    }
    for (int idx = tid; idx < TC * 32; idx += 256) {
        int t = idx >> 5, c = idx & 31;
        float v = g_dbl[(size_t)(m0 + t) * 48 + 16 + c];
        if (c < 16) sB[t * 16 + c] = v;
        else        sC[t * 16 + (c - 16)] = v;
    }
    __syncthreads();

    int warp = tid >> 5, lane = tid & 31;
    int half = lane >> 4, n = lane & 15;
    int dd = warp * 2 + half;
    int d  = d0 + dd;

    float An = -__expf(A_log[d * DST + n]);
    float h, aP = 1.f;
    if (PHASE) h = g_h0[(((size_t)b * NCH + ch) * DIN + d) * DST + n];
    else       h = 0.f;
    float Dv = PHASE ? Dp[d] : 0.f;

    #pragma unroll 4
    for (int t = 0; t < TC; t++) {
        float de = sD[t * 16 + dd];
        float ut = sU[t * 16 + dd];
        float Bn = sB[t * 16 + n];
        float dA = __expf(de * An);
        h = fmaf(dA, h, de * ut * Bn);
        if (PHASE) {
            float p = h * sC[t * 16 + n];
            p += __shfl_xor_sync(~0u, p, 8, 16);
            p += __shfl_xor_sync(~0u, p, 4, 16);
            p += __shfl_xor_sync(~0u, p, 2, 16);
            p += __shfl_xor_sync(~0u, p, 1, 16);
            if (n == 0) {
                float zt = sZ[t * 16 + dd];
                float yv = p + ut * Dv;
                yv *= zt / (1.f + __expf(-zt));
                sY[t * 16 + dd] = yv;
            }
        } else {
            aP *= dA;
        }
    }

    if (PHASE) {
        __syncthreads();
        for (int idx = tid; idx < TC * 16; idx += 256) {
            int t = idx >> 4, ddw = idx & 15;
            g_y[(size_t)(m0 + t) * DIN + d0 + ddw] = sY[idx];
        }
    } else {
        size_t o = (((size_t)b * NCH + ch) * DIN + d) * DST + n;
        g_hE[o] = h;
        g_aP[o] = aP;
    }
}

__global__ __launch_bounds__(256) void scan_combine()
{
    int idx = blockIdx.x * 256 + threadIdx.x;
    if (idx >= BSZ * DIN * DST) return;
    int b  = idx / (DIN * DST);
    int dn = idx % (DIN * DST);
    float h = 0.f;
    #pragma unroll 4
    for (int ch = 0; ch < NCH; ch++) {
        size_t o = ((size_t)b * NCH + ch) * (DIN * DST) + dn;
        g_h0[o] = h;
        h = fmaf(g_aP[o], h, g_hE[o]);
    }
}

// ============================================================
// launch
// ============================================================
extern "C" void kernel_launch(void* const* d_in, const int* in_sizes, int n_in,
                              void* d_out, int out_size)
{
    const float* x        = (const float*)d_in[0];
    const float* pe       = (const float*)d_in[1];
    const float* norm_w   = (const float*)d_in[3];
    const float* norm_b   = (const float*)d_in[4];
    const float* in_proj  = (const float*)d_in[5];
    const float* conv_w   = (const float*)d_in[6];
    const float* conv_b   = (const float*)d_in[7];
    const float* x_proj   = (const float*)d_in[8];
    const float* dt_proj  = (const float*)d_in[9];
    const float* dt_b     = (const float*)d_in[10];
    const float* A_log    = (const float*)d_in[11];
    const float* Dp       = (const float*)d_in[12];
    const float* out_proj = (const float*)d_in[13];
    float* out = (float*)d_out;

    float* xn  = nullptr; cudaGetSymbolAddress((void**)&xn,  g_xn);
    float* xz  = nullptr; cudaGetSymbolAddress((void**)&xz,  g_xz);
    float* u   = nullptr; cudaGetSymbolAddress((void**)&u,   g_u);
    float* dbl = nullptr; cudaGetSymbolAddress((void**)&dbl, g_dbl);
    float* y   = nullptr; cudaGetSymbolAddress((void**)&y,   g_y);

    // 1. pe + layernorm
    ln_kernel<<<dim3(LSEQ / 32, BSZ), 256>>>(x, pe, norm_w, norm_b);

    // 2. in_proj: xz[16384,1024] = xn[16384,256] @ in_proj^T
    mmagemm<128, 0><<<dim3(1024 / 128, NTOK / 128), 256>>>(
        xn, in_proj, xz, DIMC, 2 * DIN, 2 * DIN);

    // 3. conv + silu
    conv_kernel<<<(NTOK * DIN) / 256, 256>>>(conv_w, conv_b);

    // 4. x_proj: dbl[16384,48] = u @ x_proj^T  (N_TILE=64)
    mmagemm<64, 0><<<dim3(1, NTOK / 128), 256>>>(
        u, x_proj, dbl, DIN, 48, 48);

    // 5. dt_proj + softplus
    wdt_transpose_kernel<<<(DIN * DTR + 255) / 256, 256>>>(dt_proj);
    dt_kernel<<<NTOK, 512>>>(dt_b);

    // 6. chunked parallel scan
    scan_phase<0><<<dim3(NCH, 32, BSZ), 256>>>(A_log, Dp);
    scan_combine<<<(BSZ * DIN * DST) / 256, 256>>>();
    scan_phase<1><<<dim3(NCH, 32, BSZ), 256>>>(A_log, Dp);

    // 7. out_proj: A = out_proj_w (channels as M), B = g_y (tokens as N)
    mmagemm<128, 1><<<dim3(NTOK / 128, DIMC / 128), 256>>>(
        out_proj, y, out, DIN, NTOK, 0);
}

// round 8
// speedup vs baseline: 1.2926x; 1.0098x over previous
#include <cuda_runtime.h>
#include <cuda_bf16.h>
#include <math.h>
#include <stdint.h>

#define BSZ 4
#define DIMC 256
#define LSEQ 4096
#define DIN 512
#define DST 16
#define DTR 16
#define NTOK (BSZ * LSEQ)   // 16384
#define TC 128              // scan chunk length
#define NCH (LSEQ / TC)     // 32 chunks

// -------- scratch (device globals; no allocation) --------
__device__ float g_xn[NTOK * DIMC];
__device__ float g_xz[NTOK * 2 * DIN];    // xi | z
__device__ float g_u[NTOK * DIN];
__device__ float g_dbl[NTOK * 48];        // dt|B|C
__device__ float g_delta[NTOK * DIN];
__device__ float g_y[NTOK * DIN];
__device__ float g_hE[BSZ * NCH * DIN * DST];
__device__ float g_aP[BSZ * NCH * DIN * DST];
__device__ float g_h0[BSZ * NCH * DIN * DST];

// ============================================================
// helpers
// ============================================================
__device__ __forceinline__ uint32_t pack2(float a, float b) {
    __nv_bfloat162 t = __floats2bfloat162_rn(a, b);
    return *reinterpret_cast<uint32_t*>(&t);
}

__device__ __forceinline__ void hilo4(float4 v, uint2& hi, uint2& lo) {
    float hx = __bfloat162float(__float2bfloat16(v.x));
    float hy = __bfloat162float(__float2bfloat16(v.y));
    float hz = __bfloat162float(__float2bfloat16(v.z));
    float hw = __bfloat162float(__float2bfloat16(v.w));
    hi.x = pack2(hx, hy);
    hi.y = pack2(hz, hw);
    lo.x = pack2(v.x - hx, v.y - hy);
    lo.y = pack2(v.z - hz, v.w - hw);
}

__device__ __forceinline__ void mma16(float* d, const uint32_t* a,
                                      uint32_t b0, uint32_t b1) {
    asm volatile(
        "mma.sync.aligned.m16n8k16.row.col.f32.bf16.bf16.f32 "
        "{%0,%1,%2,%3}, {%4,%5,%6,%7}, {%8,%9}, {%0,%1,%2,%3};"
        : "+f"(d[0]), "+f"(d[1]), "+f"(d[2]), "+f"(d[3])
        : "r"(a[0]), "r"(a[1]), "r"(a[2]), "r"(a[3]), "r"(b0), "r"(b1));
}

// ============================================================
// split-bf16 (3-term) mma GEMM: C[M,N] = A[M,K] * B[N,K]^T
//   CTA tile M_TILE x N_TILE, BK=32, 8 warps
//   OUT_MODE 0: C[m*ldC + n] row-major
//   OUT_MODE 1: out[b][c][l]; m = channel c, n = global token (b,l)
// ============================================================
#define SROWB 80                    // bytes per tile row (40 bf16)

template<int M_TILE, int N_TILE, int OUT_MODE>
__global__ __launch_bounds__(256, 2) void mmagemm(
    const float* __restrict__ Ag, const float* __restrict__ Bg,
    float* __restrict__ C, int K, int bRows, int ldC)
{
    constexpr int WM = M_TILE / 32;             // warps along M
    constexpr int WN = 8 / WM;                  // warps along N
    constexpr int TN = N_TILE / (WN * 8);       // 8-wide n-frags per warp
    constexpr int NA = M_TILE * 8 / 256;        // A float4 quads per thread
    constexpr int NB = N_TILE * 8 / 256;        // B float4 quads per thread
    constexpr int TA_B = M_TILE * SROWB;
    constexpr int TB_B = N_TILE * SROWB;
    constexpr int AH = 0, AL = TA_B, BH = 2 * TA_B, BL = 2 * TA_B + TB_B;

    __shared__ char sm[2 * TA_B + 2 * TB_B];

    const int tid  = threadIdx.x;
    const int lane = tid & 31, wid = tid >> 5;
    const int gid  = lane >> 2, tig = lane & 3;
    const int wm   = wid % WM,  wn  = wid / WM;

    const int m0 = blockIdx.y * M_TILE;
    const int n0 = blockIdx.x * N_TILE;
    const int NC = K >> 5;

    float acc[2][TN][4];
    #pragma unroll
    for (int i = 0; i < 2; i++)
        #pragma unroll
        for (int j = 0; j < TN; j++)
            #pragma unroll
            for (int k = 0; k < 4; k++) acc[i][j][k] = 0.f;

    float4 avA[NA], avB[NB];

    auto ldg_regs = [&](int ck) {
        const int k0 = ck * 32;
        #pragma unroll
        for (int i = 0; i < NA; i++) {
            int idx = tid + (i << 8);
            int row = idx >> 3, q = idx & 7;
            avA[i] = *(const float4*)(Ag + (size_t)(m0 + row) * K + k0 + q * 4);
        }
        #pragma unroll
        for (int i = 0; i < NB; i++) {
            int idx = tid + (i << 8);
            int row = idx >> 3, q = idx & 7;
            if (n0 + row < bRows)
                avB[i] = *(const float4*)(Bg + (size_t)(n0 + row) * K + k0 + q * 4);
            else
                avB[i] = make_float4(0.f, 0.f, 0.f, 0.f);
        }
    };

    auto sts_regs = [&]() {
        #pragma unroll
        for (int i = 0; i < NA; i++) {
            int idx = tid + (i << 8);
            int row = idx >> 3, q = idx & 7;
            int byte = row * SROWB + q * 8;
            uint2 hi, lo;
            hilo4(avA[i], hi, lo);
            *(uint2*)(sm + AH + byte) = hi;
            *(uint2*)(sm + AL + byte) = lo;
        }
        #pragma unroll
        for (int i = 0; i < NB; i++) {
            int idx = tid + (i << 8);
            int row = idx >> 3, q = idx & 7;
            int byte = row * SROWB + q * 8;
            uint2 hi, lo;
            hilo4(avB[i], hi, lo);
            *(uint2*)(sm + BH + byte) = hi;
            *(uint2*)(sm + BL + byte) = lo;
        }
    };

    ldg_regs(0);

    for (int ck = 0; ck < NC; ck++) {
        sts_regs();
        __syncthreads();
        if (ck + 1 < NC) ldg_regs(ck + 1);

        #pragma unroll
        for (int ks = 0; ks < 2; ks++) {
            const int kb = ks * 32 + tig * 4;   // byte offset within row
            uint32_t ah[2][4], al[2][4];
            #pragma unroll
            for (int tm = 0; tm < 2; tm++) {
                int r0 = (wm * 32 + tm * 16 + gid) * SROWB;
                ah[tm][0] = *(const uint32_t*)(sm + AH + r0 + kb);
                ah[tm][1] = *(const uint32_t*)(sm + AH + r0 + 8 * SROWB + kb);
                ah[tm][2] = *(const uint32_t*)(sm + AH + r0 + kb + 16);
                ah[tm][3] = *(const uint32_t*)(sm + AH + r0 + 8 * SROWB + kb + 16);
                al[tm][0] = *(const uint32_t*)(sm + AL + r0 + kb);
                al[tm][1] = *(const uint32_t*)(sm + AL + r0 + 8 * SROWB + kb);
                al[tm][2] = *(const uint32_t*)(sm + AL + r0 + kb + 16);
                al[tm][3] = *(const uint32_t*)(sm + AL + r0 + 8 * SROWB + kb + 16);
            }
            #pragma unroll
            for (int tn = 0; tn < TN; tn++) {
                int rb = (wn * (N_TILE / WN) + tn * 8 + gid) * SROWB;
                uint32_t bh0 = *(const uint32_t*)(sm + BH + rb + kb);
                uint32_t bh1 = *(const uint32_t*)(sm + BH + rb + kb + 16);
                uint32_t bl0 = *(const uint32_t*)(sm + BL + rb + kb);
                uint32_t bl1 = *(const uint32_t*)(sm + BL + rb + kb + 16);
                #pragma unroll
                for (int tm = 0; tm < 2; tm++) {
                    mma16(acc[tm][tn], ah[tm], bh0, bh1);
                    mma16(acc[tm][tn], al[tm], bh0, bh1);
                    mma16(acc[tm][tn], ah[tm], bl0, bl1);
                }
            }
        }
        __syncthreads();
    }

    #pragma unroll
    for (int tm = 0; tm < 2; tm++) {
        int m = m0 + wm * 32 + tm * 16 + gid;
        #pragma unroll
        for (int tn = 0; tn < TN; tn++) {
            int n = n0 + wn * (N_TILE / WN) + tn * 8 + tig * 2;
            if (OUT_MODE == 0) {
                if (n + 2 <= bRows) {
                    float2 v0 = make_float2(acc[tm][tn][0], acc[tm][tn][1]);
                    float2 v1 = make_float2(acc[tm][tn][2], acc[tm][tn][3]);
                    *(float2*)&C[(size_t)m * ldC + n] = v0;
                    *(float2*)&C[(size_t)(m + 8) * ldC + n] = v1;
                }
            } else {
                int bb = n >> 12;
                int l  = n & 4095;
                size_t base = ((size_t)bb * DIMC + m) * LSEQ + l;
                float2 v0 = make_float2(acc[tm][tn][0], acc[tm][tn][1]);
                float2 v1 = make_float2(acc[tm][tn][2], acc[tm][tn][3]);
                *(float2*)&C[base] = v0;
                *(float2*)&C[base + (size_t)8 * LSEQ] = v1;
            }
        }
    }
}

// ============================================================
// 1. flatten + pe + LayerNorm  -> g_xn (token-major [m][c])
// ============================================================
__global__ __launch_bounds__(256) void ln_kernel(
    const float* __restrict__ x, const float* __restrict__ pe,
    const float* __restrict__ nw, const float* __restrict__ nb)
{
    __shared__ float sx[DIMC][33];
    int b  = blockIdx.y;
    int l0 = blockIdx.x * 32;
    int tid = threadIdx.x;

    const float* xb = x + (size_t)b * DIMC * LSEQ;
    for (int idx = tid; idx < DIMC * 32; idx += 256) {
        int c = idx >> 5, li = idx & 31;
        sx[c][li] = xb[(size_t)c * LSEQ + l0 + li];
    }
    __syncthreads();

    int warp = tid >> 5, lane = tid & 31;
    for (int tok = warp; tok < 32; tok += 8) {
        int l = l0 + tok;
        float v[8];
        float s = 0.f;
        #pragma unroll
        for (int k = 0; k < 8; k++) {
            int c = lane + 32 * k;
            v[k] = sx[c][tok] + pe[(size_t)l * DIMC + c];
            s += v[k];
        }
        #pragma unroll
        for (int off = 16; off; off >>= 1) s += __shfl_xor_sync(~0u, s, off);
        float mu = s * (1.f / DIMC);
        float vs = 0.f;
        #pragma unroll
        for (int k = 0; k < 8; k++) { float d = v[k] - mu; vs += d * d; }
        #pragma unroll
        for (int off = 16; off; off >>= 1) vs += __shfl_xor_sync(~0u, vs, off);
        float inv = rsqrtf(vs * (1.f / DIMC) + 1e-5f);
        int m = b * LSEQ + l;
        #pragma unroll
        for (int k = 0; k < 8; k++) {
            int c = lane + 32 * k;
            g_xn[(size_t)m * DIMC + c] = (v[k] - mu) * inv * nw[c] + nb[c];
        }
    }
}

// ============================================================
// 3. causal conv1d(k=4) + bias + SiLU  -> g_u
//    thread = 4 consecutive tokens of one channel (sliding window)
// ============================================================
__global__ __launch_bounds__(256) void conv_kernel(
    const float* __restrict__ cw, const float* __restrict__ cb)
{
    int idx = blockIdx.x * 256 + threadIdx.x;   // over (NTOK/4)*DIN
    int e = idx & 511;
    int q = idx >> 9;           // token quad 0..4095
    int m0 = q * 4;
    int l0 = m0 & 4095;

    float w0 = cw[e * 4 + 0], w1 = cw[e * 4 + 1];
    float w2 = cw[e * 4 + 2], w3 = cw[e * 4 + 3];
    float bias = cb[e];

    float xv[7];
    #pragma unroll
    for (int j = 0; j < 7; j++) {
        int l = l0 - 3 + j;
        xv[j] = (l >= 0) ? g_xz[(size_t)(m0 - 3 + j) * 1024 + e] : 0.f;
    }
    #pragma unroll
    for (int t = 0; t < 4; t++) {
        float acc = bias;
        acc = fmaf(xv[t],     w0, acc);
        acc = fmaf(xv[t + 1], w1, acc);
        acc = fmaf(xv[t + 2], w2, acc);
        acc = fmaf(xv[t + 3], w3, acc);
        g_u[(size_t)(m0 + t) * 512 + e] = acc / (1.f + __expf(-acc));
    }
}

// ============================================================
// 4. dt_proj + softplus: 128 CTAs x 128 tokens, weights in smem
// ============================================================
#define DTTOK 128
__global__ __launch_bounds__(256) void dt_kernel(
    const float* __restrict__ dtw, const float* __restrict__ dtb)
{
    __shared__ float swt[16][512];   // wdtT[r][d]
    __shared__ float sb[512];
    __shared__ float sdt[DTTOK][16];

    int m0 = blockIdx.x * DTTOK;
    int tid = threadIdx.x;

    for (int i = tid; i < 512 * 16; i += 256) {
        int d = i >> 4, r = i & 15;
        swt[r][d] = dtw[i];
    }
    for (int i = tid; i < 512; i += 256) sb[i] = dtb[i];
    for (int i = tid; i < DTTOK * 16; i += 256) {
        int t = i >> 4, r = i & 15;
        sdt[t][r] = g_dbl[(size_t)(m0 + t) * 48 + r];
    }
    __syncthreads();

    int d = tid * 2;
    float b0 = sb[d], b1 = sb[d + 1];
    for (int t = 0; t < DTTOK; t++) {
        float4 dv0 = *(float4*)&sdt[t][0];
        float4 dv1 = *(float4*)&sdt[t][4];
        float4 dv2 = *(float4*)&sdt[t][8];
        float4 dv3 = *(float4*)&sdt[t][12];
        float dt[16] = {dv0.x, dv0.y, dv0.z, dv0.w, dv1.x, dv1.y, dv1.z, dv1.w,
                        dv2.x, dv2.y, dv2.z, dv2.w, dv3.x, dv3.y, dv3.z, dv3.w};
        float acc0 = b0, acc1 = b1;
        #pragma unroll
        for (int r = 0; r < 16; r++) {
            float2 w = *(float2*)&swt[r][d];
            acc0 = fmaf(dt[r], w.x, acc0);
            acc1 = fmaf(dt[r], w.y, acc1);
        }
        float sp0 = (acc0 > 20.f) ? acc0 : log1pf(__expf(acc0));
        float sp1 = (acc1 > 20.f) ? acc1 : log1pf(__expf(acc1));
        *(float2*)&g_delta[(size_t)(m0 + t) * 512 + d] = make_float2(sp0, sp1);
    }
}

// ============================================================
// 5. chunked parallel selective scan
// ============================================================
template<int PHASE>
__global__ __launch_bounds__(256) void scan_phase(
    const float* __restrict__ A_log, const float* __restrict__ Dp)
{
    __shared__ float sD[TC * 16];
    __shared__ float sU[TC * 16];
    __shared__ float sB[TC * 16];
    __shared__ float sC[TC * 16];
    __shared__ float sZ[TC * 16];
    __shared__ float sY[TC * 16];

    int ch   = blockIdx.x;
    int dgrp = blockIdx.y;
    int b    = blockIdx.z;
    int tid  = threadIdx.x;
    int d0   = dgrp * 16;
    int m0   = b * LSEQ + ch * TC;

    for (int idx = tid; idx < TC * 16; idx += 256) {
        int t = idx >> 4, dd = idx & 15;
        size_t g = (size_t)(m0 + t) * DIN + d0 + dd;
        sD[idx] = g_delta[g];
        sU[idx] = g_u[g];
        if (PHASE) sZ[idx] = g_xz[(size_t)(m0 + t) * 1024 + DIN + d0 + dd];
    }
    for (int idx = tid; idx < TC * 32; idx += 256) {
        int t = idx >> 5, c = idx & 31;
        float v = g_dbl[(size_t)(m0 + t) * 48 + 16 + c];
        if (c < 16) sB[t * 16 + c] = v;
        else        sC[t * 16 + (c - 16)] = v;
    }
    __syncthreads();

    int warp = tid >> 5, lane = tid & 31;
    int half = lane >> 4, n = lane & 15;
    int dd = warp * 2 + half;
    int d  = d0 + dd;

    float An = -__expf(A_log[d * DST + n]);
    float h, aP = 1.f;
    if (PHASE) h = g_h0[(((size_t)b * NCH + ch) * DIN + d) * DST + n];
    else       h = 0.f;
    float Dv = PHASE ? Dp[d] : 0.f;

    #pragma unroll 4
    for (int t = 0; t < TC; t++) {
        float de = sD[t * 16 + dd];
        float ut = sU[t * 16 + dd];
        float Bn = sB[t * 16 + n];
        float dA = __expf(de * An);
        h = fmaf(dA, h, de * ut * Bn);
        if (PHASE) {
            float p = h * sC[t * 16 + n];
            p += __shfl_xor_sync(~0u, p, 8, 16);
            p += __shfl_xor_sync(~0u, p, 4, 16);
            p += __shfl_xor_sync(~0u, p, 2, 16);
            p += __shfl_xor_sync(~0u, p, 1, 16);
            if (n == 0) {
                float zt = sZ[t * 16 + dd];
                float yv = p + ut * Dv;
                yv *= zt / (1.f + __expf(-zt));
                sY[t * 16 + dd] = yv;
            }
        } else {
            aP *= dA;
        }
    }

    if (PHASE) {
        __syncthreads();
        for (int idx = tid; idx < TC * 16; idx += 256) {
            int t = idx >> 4, ddw = idx & 15;
            g_y[(size_t)(m0 + t) * DIN + d0 + ddw] = sY[idx];
        }
    } else {
        size_t o = (((size_t)b * NCH + ch) * DIN + d) * DST + n;
        g_hE[o] = h;
        g_aP[o] = aP;
    }
}

__global__ __launch_bounds__(256) void scan_combine()
{
    int idx = blockIdx.x * 256 + threadIdx.x;
    if (idx >= BSZ * DIN * DST) return;
    int b  = idx / (DIN * DST);
    int dn = idx % (DIN * DST);
    float h = 0.f;
    #pragma unroll 4
    for (int ch = 0; ch < NCH; ch++) {
        size_t o = ((size_t)b * NCH + ch) * (DIN * DST) + dn;
        g_h0[o] = h;
        h = fmaf(g_aP[o], h, g_hE[o]);
    }
}

// ============================================================
// launch
// ============================================================
extern "C" void kernel_launch(void* const* d_in, const int* in_sizes, int n_in,
                              void* d_out, int out_size)
{
    const float* x        = (const float*)d_in[0];
    const float* pe       = (const float*)d_in[1];
    const float* norm_w   = (const float*)d_in[3];
    const float* norm_b   = (const float*)d_in[4];
    const float* in_proj  = (const float*)d_in[5];
    const float* conv_w   = (const float*)d_in[6];
    const float* conv_b   = (const float*)d_in[7];
    const float* x_proj   = (const float*)d_in[8];
    const float* dt_proj  = (const float*)d_in[9];
    const float* dt_b     = (const float*)d_in[10];
    const float* A_log    = (const float*)d_in[11];
    const float* Dp       = (const float*)d_in[12];
    const float* out_proj = (const float*)d_in[13];
    float* out = (float*)d_out;

    float* xn  = nullptr; cudaGetSymbolAddress((void**)&xn,  g_xn);
    float* xz  = nullptr; cudaGetSymbolAddress((void**)&xz,  g_xz);
    float* u   = nullptr; cudaGetSymbolAddress((void**)&u,   g_u);
    float* dbl = nullptr; cudaGetSymbolAddress((void**)&dbl, g_dbl);
    float* y   = nullptr; cudaGetSymbolAddress((void**)&y,   g_y);

    // 1. pe + layernorm
    ln_kernel<<<dim3(LSEQ / 32, BSZ), 256>>>(x, pe, norm_w, norm_b);

    // 2. in_proj: xz[16384,1024] = xn[16384,256] @ in_proj^T
    mmagemm<128, 128, 0><<<dim3(1024 / 128, NTOK / 128), 256>>>(
        xn, in_proj, xz, DIMC, 2 * DIN, 2 * DIN);

    // 3. conv + silu
    conv_kernel<<<(NTOK / 4) * DIN / 256, 256>>>(conv_w, conv_b);

    // 4. x_proj: dbl[16384,48] = u @ x_proj^T  (64x64 tiles, 256 CTAs)
    mmagemm<64, 64, 0><<<dim3(1, NTOK / 64), 256>>>(
        u, x_proj, dbl, DIN, 48, 48);

    // 5. dt_proj + softplus (weights staged in smem, 128 CTAs)
    dt_kernel<<<NTOK / DTTOK, 256>>>(dt_proj, dt_b);

    // 6. chunked parallel scan
    scan_phase<0><<<dim3(NCH, 32, BSZ), 256>>>(A_log, Dp);
    scan_combine<<<(BSZ * DIN * DST) / 256, 256>>>();
    scan_phase<1><<<dim3(NCH, 32, BSZ), 256>>>(A_log, Dp);

    // 7. out_proj: A = out_proj_w (channels as M), B = g_y (tokens as N)
    mmagemm<128, 128, 1><<<dim3(NTOK / 128, DIMC / 128), 256>>>(
        out_proj, y, out, DIN, NTOK, 0);
}